// round 14
// baseline (speedup 1.0000x reference)
#include <cuda_runtime.h>
#include <cstdint>

typedef unsigned long long u64;

#define NB   8192
#define SS   64
#define NXX  4
#define NSF  5
#define HH   32
#define WPB  4          // warps per block
#define SPW  3          // batch streams per warp
#define BPB  (WPB*SPW)  // 12 batch elements per block
#define CH   4          // layer-2 time chunk
#define FULLMASK 0xffffffffu

// ---------- packed f32x2 helpers ----------
static __device__ __forceinline__ u64 ffma2(u64 a, u64 b, u64 c) {
    u64 d; asm("fma.rn.f32x2 %0, %1, %2, %3;" : "=l"(d) : "l"(a), "l"(b), "l"(c)); return d;
}
static __device__ __forceinline__ u64 pk2(float lo, float hi) {
    u64 r; asm("mov.b64 %0, {%1, %2};" : "=l"(r) : "f"(lo), "f"(hi)); return r;
}
static __device__ __forceinline__ u64 pklo(float lo) {
    u64 r; asm("mov.b64 %0, {%1, %2};" : "=l"(r) : "f"(lo), "f"(0.0f)); return r;
}
static __device__ __forceinline__ void up2(u64 v, float& lo, float& hi) {
    asm("mov.b64 {%0, %1}, %2;" : "=f"(lo), "=f"(hi) : "l"(v));
}
static __device__ __forceinline__ float hsum2(u64 v) {
    float x, y; up2(v, x, y); return x + y;
}

// ---------- fast activations (MUFU.TANH) ----------
static __device__ __forceinline__ float tanh_ap(float x) {
    float r; asm("tanh.approx.f32 %0, %1;" : "=f"(r) : "f"(x)); return r;
}
static __device__ __forceinline__ float sigm(float x) {
    return fmaf(tanh_ap(0.5f * x), 0.5f, 0.5f);
}

// fill full [4H,H] weight matrix into WR[64] pairs from GLOBAL (L1-cached)
static __device__ __forceinline__ void fill_WR(u64 WR[64], const float* __restrict__ M, int lane) {
    #pragma unroll
    for (int g = 0; g < 4; ++g) {
        const float* src = M + (g * HH + lane) * HH;
        #pragma unroll
        for (int qq = 0; qq < 8; ++qq) {
            ulonglong2 v = *(const ulonglong2*)(src + qq * 4);
            WR[g * 16 + 2 * qq]     = v.x;
            WR[g * 16 + 2 * qq + 1] = v.y;
        }
    }
}

// ---- shared memory (bytes) ----
// sy  : float[12][64][32]   layer-1 outputs -> layer-2 h2    98304
// hb  : float[12][2][32]    h broadcast double buffers        3072
// swo : float[32]           w_out staged                       128
#define OFF_SY   0
#define OFF_HB   98304
#define OFF_SWO  (98304 + 3072)
#define SMEM_BYTES (OFF_SWO + 128)

__global__ void __launch_bounds__(WPB * 32, 2)
lstm_fused12(const float* __restrict__ x_main,
             const float* __restrict__ x_sfc,
             const float* __restrict__ w_sfc1, const float* __restrict__ b_sfc1,
             const float* __restrict__ w_sfc2, const float* __restrict__ b_sfc2,
             const float* __restrict__ w_ih1,  const float* __restrict__ w_hh1,
             const float* __restrict__ b_ih1,  const float* __restrict__ b_hh1,
             const float* __restrict__ w_ih2,  const float* __restrict__ w_hh2,
             const float* __restrict__ b_ih2,  const float* __restrict__ b_hh2,
             const float* __restrict__ w_out,  const float* __restrict__ b_out,
             float* __restrict__ out)
{
    extern __shared__ char smem[];
    float* sy  = (float*)(smem + OFF_SY);
    float* hb  = (float*)(smem + OFF_HB);
    float* swo = (float*)(smem + OFF_SWO);

    const int tid  = threadIdx.x;
    const int wid  = tid >> 5;
    const int lane = tid & 31;
    const int bbase = blockIdx.x * BPB + wid * SPW;
    const int ls0   = wid * SPW;

    if (tid < 32) swo[tid] = w_out[tid];

    // stream validity (last block may run past NB)
    int  bi[SPW];
    bool vl[SPW];
    #pragma unroll
    for (int m = 0; m < SPW; ++m) {
        const int b = bbase + m;
        vl[m] = (b < NB);
        bi[m] = vl[m] ? b : (NB - 1);
    }

    // ---- layer-1 weights -> registers ----
    u64 WR[64];
    fill_WR(WR, w_hh1, lane);
    u64 wih[4][2], bias1p[4];
    #pragma unroll
    for (int g = 0; g < 4; ++g) {
        const int row = g * HH + lane;
        ulonglong2 vi = *(const ulonglong2*)(w_ih1 + row * NXX);
        wih[g][0] = vi.x;
        wih[g][1] = vi.y;
        bias1p[g] = pklo(b_ih1[row] + b_hh1[row]);
    }

    // ---- initial state from surface MLPs ----
    float cs[SPW];
    #pragma unroll
    for (int m = 0; m < SPW; ++m) {
        float a1 = b_sfc1[lane], a2 = b_sfc2[lane];
        #pragma unroll
        for (int k = 0; k < NSF; ++k) {
            const float sv = x_sfc[bi[m] * NSF + k];
            a1 += sv * w_sfc1[lane * NSF + k];
            a2 += sv * w_sfc2[lane * NSF + k];
        }
        hb[(ls0 + m) * 64 + lane] = tanh_ap(a1);
        cs[m] = tanh_ap(a2);
    }
    __syncwarp();
    int buf = 0;

    // ================= layer 1: time-reversed scan, 3 interleaved streams =================
    #pragma unroll 1
    for (int t = 0; t < SS; ++t) {
        const int s = SS - 1 - t;
        ulonglong2 xv[SPW];
        #pragma unroll
        for (int m = 0; m < SPW; ++m)
            xv[m] = *(const ulonglong2*)(x_main + (size_t)bi[m] * (SS * NXX) + s * NXX);

        u64 A[SPW][4];
        #pragma unroll
        for (int m = 0; m < SPW; ++m)
            #pragma unroll
            for (int g = 0; g < 4; ++g)
                A[m][g] = bias1p[g];

        #pragma unroll
        for (int q = 0; q < 8; ++q) {
            #pragma unroll
            for (int m = 0; m < SPW; ++m) {
                const ulonglong2 hv =
                    ((const ulonglong2*)(hb + (ls0 + m) * 64 + buf * 32))[q];
                #pragma unroll
                for (int g = 0; g < 4; ++g) {
                    A[m][g] = ffma2(hv.x, WR[g * 16 + 2 * q],     A[m][g]);
                    A[m][g] = ffma2(hv.y, WR[g * 16 + 2 * q + 1], A[m][g]);
                }
            }
        }
        // x projection (LDG issued at loop top, consumed here)
        #pragma unroll
        for (int m = 0; m < SPW; ++m)
            #pragma unroll
            for (int g = 0; g < 4; ++g) {
                A[m][g] = ffma2(xv[m].x, wih[g][0], A[m][g]);
                A[m][g] = ffma2(xv[m].y, wih[g][1], A[m][g]);
            }

        #pragma unroll
        for (int m = 0; m < SPW; ++m) {
            const float iv = sigm(hsum2(A[m][0]));
            const float fv = sigm(hsum2(A[m][1]));
            const float gv = tanh_ap(hsum2(A[m][2]));
            const float ov = sigm(hsum2(A[m][3]));
            cs[m] = fv * cs[m] + iv * gv;
            const float h = ov * tanh_ap(cs[m]);
            sy[(ls0 + m) * (SS * HH) + s * HH + lane] = h;
            hb[(ls0 + m) * 64 + (buf ^ 1) * 32 + lane] = h;
        }
        __syncwarp();
        buf ^= 1;
    }

    // ================= layer 2: forward scan =================
    float bias2[4];
    #pragma unroll
    for (int g = 0; g < 4; ++g)
        bias2[g] = b_ih2[g * HH + lane] + b_hh2[g * HH + lane];

    #pragma unroll
    for (int m = 0; m < SPW; ++m) {
        cs[m] = 0.0f;
        hb[(ls0 + m) * 64 + buf * 32 + lane] = 0.0f;
    }
    __syncwarp();

    u64 xg[SPW][CH][2];

    #pragma unroll 1
    for (int chk = 0; chk < SS / CH; ++chk) {
        const int t0 = chk * CH;

        // ---- phase A: input projection (w_ih2 -> WR from global) ----
        fill_WR(WR, w_ih2, lane);
        #pragma unroll
        for (int tt = 0; tt < CH; ++tt) {
            u64 A[SPW][4];
            #pragma unroll
            for (int m = 0; m < SPW; ++m)
                #pragma unroll
                for (int g = 0; g < 4; ++g)
                    A[m][g] = 0ull;
            #pragma unroll
            for (int q = 0; q < 8; ++q) {
                #pragma unroll
                for (int m = 0; m < SPW; ++m) {
                    const ulonglong2 hv =
                        ((const ulonglong2*)(sy + (ls0 + m) * (SS * HH) + (t0 + tt) * HH))[q];
                    #pragma unroll
                    for (int g = 0; g < 4; ++g) {
                        A[m][g] = ffma2(hv.x, WR[g * 16 + 2 * q],     A[m][g]);
                        A[m][g] = ffma2(hv.y, WR[g * 16 + 2 * q + 1], A[m][g]);
                    }
                }
            }
            #pragma unroll
            for (int m = 0; m < SPW; ++m) {
                xg[m][tt][0] = pk2(hsum2(A[m][0]) + bias2[0], hsum2(A[m][1]) + bias2[1]);
                xg[m][tt][1] = pk2(hsum2(A[m][2]) + bias2[2], hsum2(A[m][3]) + bias2[3]);
            }
        }

        // ---- phase B: recurrence (w_hh2 -> WR from global) ----
        fill_WR(WR, w_hh2, lane);
        #pragma unroll
        for (int tt = 0; tt < CH; ++tt) {
            u64 A[SPW][4];
            #pragma unroll
            for (int m = 0; m < SPW; ++m) {
                float e0, e1, e2, e3;
                up2(xg[m][tt][0], e0, e1);
                up2(xg[m][tt][1], e2, e3);
                A[m][0] = pklo(e0); A[m][1] = pklo(e1);
                A[m][2] = pklo(e2); A[m][3] = pklo(e3);
            }
            #pragma unroll
            for (int q = 0; q < 8; ++q) {
                #pragma unroll
                for (int m = 0; m < SPW; ++m) {
                    const ulonglong2 hv =
                        ((const ulonglong2*)(hb + (ls0 + m) * 64 + buf * 32))[q];
                    #pragma unroll
                    for (int g = 0; g < 4; ++g) {
                        A[m][g] = ffma2(hv.x, WR[g * 16 + 2 * q],     A[m][g]);
                        A[m][g] = ffma2(hv.y, WR[g * 16 + 2 * q + 1], A[m][g]);
                    }
                }
            }
            #pragma unroll
            for (int m = 0; m < SPW; ++m) {
                const float iv = sigm(hsum2(A[m][0]));
                const float fv = sigm(hsum2(A[m][1]));
                const float gv = tanh_ap(hsum2(A[m][2]));
                const float ov = sigm(hsum2(A[m][3]));
                cs[m] = fv * cs[m] + iv * gv;
                const float h2 = ov * tanh_ap(cs[m]);
                hb[(ls0 + m) * 64 + (buf ^ 1) * 32 + lane] = h2;
                sy[(ls0 + m) * (SS * HH) + (t0 + tt) * HH + lane] = h2;  // dead y -> h2
            }
            __syncwarp();
            buf ^= 1;
        }
    }

    // ================= deferred output head =================
    const float bo = b_out[0];
    #pragma unroll 1
    for (int m = 0; m < SPW; ++m) {
        const float* sys = sy + (ls0 + m) * (SS * HH);
        float acc0 = 0.0f, acc1 = 0.0f;
        #pragma unroll
        for (int k = 0; k < HH; ++k) {
            const int idx = (k + lane) & 31;
            const float wv = swo[idx];
            acc0 = fmaf(sys[lane * HH + idx],        wv, acc0);
            acc1 = fmaf(sys[(lane + 32) * HH + idx], wv, acc1);
        }
        if (vl[m]) {
            out[(size_t)(bbase + m) * SS + lane]      = acc0 + bo;
            out[(size_t)(bbase + m) * SS + lane + 32] = acc1 + bo;
        }
    }
}

extern "C" void kernel_launch(void* const* d_in, const int* in_sizes, int n_in,
                              void* d_out, int out_size)
{
    const float* x_main = (const float*)d_in[0];
    const float* x_sfc  = (const float*)d_in[1];
    const float* w_sfc1 = (const float*)d_in[2];
    const float* b_sfc1 = (const float*)d_in[3];
    const float* w_sfc2 = (const float*)d_in[4];
    const float* b_sfc2 = (const float*)d_in[5];
    const float* w_ih1  = (const float*)d_in[6];
    const float* w_hh1  = (const float*)d_in[7];
    const float* b_ih1  = (const float*)d_in[8];
    const float* b_hh1  = (const float*)d_in[9];
    const float* w_ih2  = (const float*)d_in[10];
    const float* w_hh2  = (const float*)d_in[11];
    const float* b_ih2  = (const float*)d_in[12];
    const float* b_hh2  = (const float*)d_in[13];
    const float* w_out  = (const float*)d_in[14];
    const float* b_out  = (const float*)d_in[15];
    float* out = (float*)d_out;

    static bool attr_set = false;
    if (!attr_set) {
        cudaFuncSetAttribute(lstm_fused12, cudaFuncAttributeMaxDynamicSharedMemorySize, SMEM_BYTES);
        attr_set = true;
    }

    const int blocks = (NB + BPB - 1) / BPB;   // 683
    lstm_fused12<<<blocks, WPB * 32, SMEM_BYTES>>>(
        x_main, x_sfc, w_sfc1, b_sfc1, w_sfc2, b_sfc2,
        w_ih1, w_hh1, b_ih1, b_hh1,
        w_ih2, w_hh2, b_ih2, b_hh2,
        w_out, b_out, out);
}

// round 16
// speedup vs baseline: 1.8188x; 1.8188x over previous
#include <cuda_runtime.h>
#include <cstdint>

typedef unsigned long long u64;

#define NB   8192
#define SS   64
#define NXX  4
#define NSF  5
#define HH   32
#define WPB  4          // warps per block
#define SPW  2          // batch streams per warp
#define BPB  (WPB*SPW)  // 8 batch elements per block
#define SCH  8          // layer-2 superchunk (4 in regs + 4 in smem)
#define FULLMASK 0xffffffffu

// ---------- packed f32x2 helpers ----------
static __device__ __forceinline__ u64 ffma2(u64 a, u64 b, u64 c) {
    u64 d; asm("fma.rn.f32x2 %0, %1, %2, %3;" : "=l"(d) : "l"(a), "l"(b), "l"(c)); return d;
}
static __device__ __forceinline__ u64 pk2(float lo, float hi) {
    u64 r; asm("mov.b64 %0, {%1, %2};" : "=l"(r) : "f"(lo), "f"(hi)); return r;
}
static __device__ __forceinline__ u64 pklo(float lo) {
    u64 r; asm("mov.b64 %0, {%1, %2};" : "=l"(r) : "f"(lo), "f"(0.0f)); return r;
}
static __device__ __forceinline__ void up2(u64 v, float& lo, float& hi) {
    asm("mov.b64 {%0, %1}, %2;" : "=f"(lo), "=f"(hi) : "l"(v));
}
static __device__ __forceinline__ float hsum2(u64 v) {
    float x, y; up2(v, x, y); return x + y;
}

// ---------- fast activations (MUFU.TANH) ----------
static __device__ __forceinline__ float tanh_ap(float x) {
    float r; asm("tanh.approx.f32 %0, %1;" : "=f"(r) : "f"(x)); return r;
}
static __device__ __forceinline__ float sigm(float x) {
    return fmaf(tanh_ap(0.5f * x), 0.5f, 0.5f);
}

// fill full [4H,H] weight matrix into WR[64] pairs from GLOBAL (L1-cached)
static __device__ __forceinline__ void fill_WR_g(u64 WR[64], const float* __restrict__ M, int lane) {
    #pragma unroll
    for (int g = 0; g < 4; ++g) {
        const float* src = M + (g * HH + lane) * HH;
        #pragma unroll
        for (int qq = 0; qq < 8; ++qq) {
            ulonglong2 v = *(const ulonglong2*)(src + qq * 4);
            WR[g * 16 + 2 * qq]     = v.x;
            WR[g * 16 + 2 * qq + 1] = v.y;
        }
    }
}

// ---- shared memory (bytes) ----
// w2i : ulonglong2[8][128]       w_ih2 staged                  16384
// sy  : float[8][64][32]         layer-1 outputs -> h2         65536
// hb  : float[8][2][32]          h broadcast double buffers     2048
// swo : float[32]                w_out staged                    128
// xgs : u64[4][2][4][2][32]      xg overflow (tt 4..7)         16384
#define OFF_W2I  0
#define OFF_SY   16384
#define OFF_HB   (16384 + 65536)
#define OFF_SWO  (OFF_HB + 2048)
#define OFF_XGS  (OFF_SWO + 128)
#define SMEM_BYTES (OFF_XGS + 16384)
// lane-private xgs index: warp, stream(0/1), tt4(0..3), half(0/1)
// max index = (((3*2+1)*4+3)*2+1)*32 + 31 = 2047  -> 2048 u64 = 16384 B  ✓
#define XGS(w,s,t4,h) ((((((w)*2+(s))*4+(t4))*2+(h))*32))

__global__ void __launch_bounds__(WPB * 32, 2)
lstm_fused16(const float* __restrict__ x_main,
             const float* __restrict__ x_sfc,
             const float* __restrict__ w_sfc1, const float* __restrict__ b_sfc1,
             const float* __restrict__ w_sfc2, const float* __restrict__ b_sfc2,
             const float* __restrict__ w_ih1,  const float* __restrict__ w_hh1,
             const float* __restrict__ b_ih1,  const float* __restrict__ b_hh1,
             const float* __restrict__ w_ih2,  const float* __restrict__ w_hh2,
             const float* __restrict__ b_ih2,  const float* __restrict__ b_hh2,
             const float* __restrict__ w_out,  const float* __restrict__ b_out,
             float* __restrict__ out)
{
    extern __shared__ char smem[];
    ulonglong2* w2i = (ulonglong2*)(smem + OFF_W2I);   // [qq*128 + row]
    float* sy  = (float*)(smem + OFF_SY);
    float* hb  = (float*)(smem + OFF_HB);
    float* swo = (float*)(smem + OFF_SWO);
    u64*   xgs = (u64*)(smem + OFF_XGS);

    const int tid  = threadIdx.x;
    const int wid  = tid >> 5;
    const int lane = tid & 31;
    const int bbase = blockIdx.x * BPB + wid * SPW;
    const int ls0   = wid * SPW;

    // ---- stage w_ih2 + w_out into smem ----
    #pragma unroll 4
    for (int i = tid; i < 8 * 128; i += WPB * 32) {
        const int qq  = i >> 7;
        const int row = i & 127;
        w2i[i] = *(const ulonglong2*)(w_ih2 + row * HH + qq * 4);
    }
    if (tid < 32) swo[tid] = w_out[tid];
    __syncthreads();

    // ---- layer-1 weights -> registers ----
    u64 WR[64];    // WR[g*16 + 2qq + j]
    fill_WR_g(WR, w_hh1, lane);
    u64 wih[4][2], bias1p[4];
    #pragma unroll
    for (int g = 0; g < 4; ++g) {
        const int row = g * HH + lane;
        ulonglong2 vi = *(const ulonglong2*)(w_ih1 + row * NXX);
        wih[g][0] = vi.x;
        wih[g][1] = vi.y;
        bias1p[g] = pklo(b_ih1[row] + b_hh1[row]);
    }

    float* hb0 = hb + (ls0 + 0) * 64;
    float* hb1 = hb + (ls0 + 1) * 64;
    const float* x0 = x_main + (size_t)(bbase + 0) * (SS * NXX);
    const float* x1 = x_main + (size_t)(bbase + 1) * (SS * NXX);
    float* sy0 = sy + (ls0 + 0) * (SS * HH);
    float* sy1 = sy + (ls0 + 1) * (SS * HH);

    // ---- initial state from surface MLPs ----
    float c0s, c1s;
    {
        float a10 = b_sfc1[lane], a20 = b_sfc2[lane];
        float a11 = a10, a21 = a20;
        #pragma unroll
        for (int k = 0; k < NSF; ++k) {
            const float w1v = w_sfc1[lane * NSF + k];
            const float w2v = w_sfc2[lane * NSF + k];
            const float s0 = x_sfc[(bbase + 0) * NSF + k];
            const float s1 = x_sfc[(bbase + 1) * NSF + k];
            a10 += s0 * w1v;  a11 += s1 * w1v;
            a20 += s0 * w2v;  a21 += s1 * w2v;
        }
        hb0[lane] = tanh_ap(a10);
        hb1[lane] = tanh_ap(a11);
        c0s = tanh_ap(a20);
        c1s = tanh_ap(a21);
    }
    __syncwarp();
    int buf = 0;

    // ================= layer 1: time-reversed scan, interleaved streams =================
    #pragma unroll 1
    for (int t = 0; t < SS; ++t) {
        const int s = SS - 1 - t;
        const ulonglong2 xv0 = *(const ulonglong2*)(x0 + s * NXX);
        const ulonglong2 xv1 = *(const ulonglong2*)(x1 + s * NXX);

        u64 A00 = bias1p[0], A01 = bias1p[1], A02 = bias1p[2], A03 = bias1p[3];
        u64 A10 = bias1p[0], A11 = bias1p[1], A12 = bias1p[2], A13 = bias1p[3];

        A00 = ffma2(xv0.x, wih[0][0], A00);  A10 = ffma2(xv1.x, wih[0][0], A10);
        A00 = ffma2(xv0.y, wih[0][1], A00);  A10 = ffma2(xv1.y, wih[0][1], A10);
        A01 = ffma2(xv0.x, wih[1][0], A01);  A11 = ffma2(xv1.x, wih[1][0], A11);
        A01 = ffma2(xv0.y, wih[1][1], A01);  A11 = ffma2(xv1.y, wih[1][1], A11);
        A02 = ffma2(xv0.x, wih[2][0], A02);  A12 = ffma2(xv1.x, wih[2][0], A12);
        A02 = ffma2(xv0.y, wih[2][1], A02);  A12 = ffma2(xv1.y, wih[2][1], A12);
        A03 = ffma2(xv0.x, wih[3][0], A03);  A13 = ffma2(xv1.x, wih[3][0], A13);
        A03 = ffma2(xv0.y, wih[3][1], A03);  A13 = ffma2(xv1.y, wih[3][1], A13);

        const ulonglong2* hp0 = (const ulonglong2*)(hb0 + buf * 32);
        const ulonglong2* hp1 = (const ulonglong2*)(hb1 + buf * 32);
        #pragma unroll
        for (int q = 0; q < 8; ++q) {
            const ulonglong2 hv0 = hp0[q];
            const ulonglong2 hv1 = hp1[q];
            A00 = ffma2(hv0.x, WR[2*q],      A00);  A10 = ffma2(hv1.x, WR[2*q],      A10);
            A00 = ffma2(hv0.y, WR[2*q+1],    A00);  A10 = ffma2(hv1.y, WR[2*q+1],    A10);
            A01 = ffma2(hv0.x, WR[16+2*q],   A01);  A11 = ffma2(hv1.x, WR[16+2*q],   A11);
            A01 = ffma2(hv0.y, WR[16+2*q+1], A01);  A11 = ffma2(hv1.y, WR[16+2*q+1], A11);
            A02 = ffma2(hv0.x, WR[32+2*q],   A02);  A12 = ffma2(hv1.x, WR[32+2*q],   A12);
            A02 = ffma2(hv0.y, WR[32+2*q+1], A02);  A12 = ffma2(hv1.y, WR[32+2*q+1], A12);
            A03 = ffma2(hv0.x, WR[48+2*q],   A03);  A13 = ffma2(hv1.x, WR[48+2*q],   A13);
            A03 = ffma2(hv0.y, WR[48+2*q+1], A03);  A13 = ffma2(hv1.y, WR[48+2*q+1], A13);
        }

        const float iv0 = sigm(hsum2(A00)), fv0 = sigm(hsum2(A01));
        const float gv0 = tanh_ap(hsum2(A02)), ov0 = sigm(hsum2(A03));
        const float iv1 = sigm(hsum2(A10)), fv1 = sigm(hsum2(A11));
        const float gv1 = tanh_ap(hsum2(A12)), ov1 = sigm(hsum2(A13));
        c0s = fv0 * c0s + iv0 * gv0;
        c1s = fv1 * c1s + iv1 * gv1;
        const float h0 = ov0 * tanh_ap(c0s);
        const float h1 = ov1 * tanh_ap(c1s);
        sy0[s * HH + lane] = h0;
        sy1[s * HH + lane] = h1;
        hb0[(buf ^ 1) * 32 + lane] = h0;
        hb1[(buf ^ 1) * 32 + lane] = h1;
        __syncwarp();
        buf ^= 1;
    }

    // ================= layer 2: forward scan, superchunks of 8 =================
    float bias2[4];
    #pragma unroll
    for (int g = 0; g < 4; ++g)
        bias2[g] = b_ih2[g * HH + lane] + b_hh2[g * HH + lane];

    c0s = 0.0f; c1s = 0.0f;
    hb0[buf * 32 + lane] = 0.0f;
    hb1[buf * 32 + lane] = 0.0f;
    __syncwarp();

    u64 xg0[4][2], xg1[4][2];    // tt 0..3 in registers; tt 4..7 in xgs smem

    #pragma unroll 1
    for (int chk = 0; chk < SS / SCH; ++chk) {
        const int t0 = chk * SCH;

        // ---- phase A: input projection for 8 timesteps (w_ih2 from smem) ----
        #pragma unroll
        for (int g = 0; g < 4; ++g)
            #pragma unroll
            for (int qq = 0; qq < 8; ++qq) {
                ulonglong2 v = w2i[qq * 128 + g * 32 + lane];
                WR[g * 16 + 2 * qq]     = v.x;
                WR[g * 16 + 2 * qq + 1] = v.y;
            }
        #pragma unroll
        for (int tt = 0; tt < SCH; ++tt) {
            const ulonglong2* yp0 = (const ulonglong2*)(sy0 + (t0 + tt) * HH);
            const ulonglong2* yp1 = (const ulonglong2*)(sy1 + (t0 + tt) * HH);
            u64 A00 = 0ull, A01 = 0ull, A02 = 0ull, A03 = 0ull;
            u64 A10 = 0ull, A11 = 0ull, A12 = 0ull, A13 = 0ull;
            #pragma unroll
            for (int q = 0; q < 8; ++q) {
                const ulonglong2 hv0 = yp0[q];
                const ulonglong2 hv1 = yp1[q];
                A00 = ffma2(hv0.x, WR[2*q],      A00);  A10 = ffma2(hv1.x, WR[2*q],      A10);
                A00 = ffma2(hv0.y, WR[2*q+1],    A00);  A10 = ffma2(hv1.y, WR[2*q+1],    A10);
                A01 = ffma2(hv0.x, WR[16+2*q],   A01);  A11 = ffma2(hv1.x, WR[16+2*q],   A11);
                A01 = ffma2(hv0.y, WR[16+2*q+1], A01);  A11 = ffma2(hv1.y, WR[16+2*q+1], A11);
                A02 = ffma2(hv0.x, WR[32+2*q],   A02);  A12 = ffma2(hv1.x, WR[32+2*q],   A12);
                A02 = ffma2(hv0.y, WR[32+2*q+1], A02);  A12 = ffma2(hv1.y, WR[32+2*q+1], A12);
                A03 = ffma2(hv0.x, WR[48+2*q],   A03);  A13 = ffma2(hv1.x, WR[48+2*q],   A13);
                A03 = ffma2(hv0.y, WR[48+2*q+1], A03);  A13 = ffma2(hv1.y, WR[48+2*q+1], A13);
            }
            const u64 r00 = pk2(hsum2(A00) + bias2[0], hsum2(A01) + bias2[1]);
            const u64 r01 = pk2(hsum2(A02) + bias2[2], hsum2(A03) + bias2[3]);
            const u64 r10 = pk2(hsum2(A10) + bias2[0], hsum2(A11) + bias2[1]);
            const u64 r11 = pk2(hsum2(A12) + bias2[2], hsum2(A13) + bias2[3]);
            if (tt < 4) {
                xg0[tt][0] = r00;  xg0[tt][1] = r01;
                xg1[tt][0] = r10;  xg1[tt][1] = r11;
            } else {
                xgs[XGS(wid, 0, tt - 4, 0) + lane] = r00;
                xgs[XGS(wid, 0, tt - 4, 1) + lane] = r01;
                xgs[XGS(wid, 1, tt - 4, 0) + lane] = r10;
                xgs[XGS(wid, 1, tt - 4, 1) + lane] = r11;
            }
        }

        // ---- phase B: recurrence for 8 timesteps (w_hh2 from global, L1) ----
        fill_WR_g(WR, w_hh2, lane);
        #pragma unroll
        for (int tt = 0; tt < SCH; ++tt) {
            u64 g00, g01, g10, g11;
            if (tt < 4) {
                g00 = xg0[tt][0];  g01 = xg0[tt][1];
                g10 = xg1[tt][0];  g11 = xg1[tt][1];
            } else {
                g00 = xgs[XGS(wid, 0, tt - 4, 0) + lane];
                g01 = xgs[XGS(wid, 0, tt - 4, 1) + lane];
                g10 = xgs[XGS(wid, 1, tt - 4, 0) + lane];
                g11 = xgs[XGS(wid, 1, tt - 4, 1) + lane];
            }
            float x00, x01, x02, x03, x10, x11, x12, x13;
            up2(g00, x00, x01);
            up2(g01, x02, x03);
            up2(g10, x10, x11);
            up2(g11, x12, x13);
            u64 A00 = pklo(x00), A01 = pklo(x01), A02 = pklo(x02), A03 = pklo(x03);
            u64 A10 = pklo(x10), A11 = pklo(x11), A12 = pklo(x12), A13 = pklo(x13);

            const ulonglong2* hp0 = (const ulonglong2*)(hb0 + buf * 32);
            const ulonglong2* hp1 = (const ulonglong2*)(hb1 + buf * 32);
            #pragma unroll
            for (int q = 0; q < 8; ++q) {
                const ulonglong2 hv0 = hp0[q];
                const ulonglong2 hv1 = hp1[q];
                A00 = ffma2(hv0.x, WR[2*q],      A00);  A10 = ffma2(hv1.x, WR[2*q],      A10);
                A00 = ffma2(hv0.y, WR[2*q+1],    A00);  A10 = ffma2(hv1.y, WR[2*q+1],    A10);
                A01 = ffma2(hv0.x, WR[16+2*q],   A01);  A11 = ffma2(hv1.x, WR[16+2*q],   A11);
                A01 = ffma2(hv0.y, WR[16+2*q+1], A01);  A11 = ffma2(hv1.y, WR[16+2*q+1], A11);
                A02 = ffma2(hv0.x, WR[32+2*q],   A02);  A12 = ffma2(hv1.x, WR[32+2*q],   A12);
                A02 = ffma2(hv0.y, WR[32+2*q+1], A02);  A12 = ffma2(hv1.y, WR[32+2*q+1], A12);
                A03 = ffma2(hv0.x, WR[48+2*q],   A03);  A13 = ffma2(hv1.x, WR[48+2*q],   A13);
                A03 = ffma2(hv0.y, WR[48+2*q+1], A03);  A13 = ffma2(hv1.y, WR[48+2*q+1], A13);
            }
            const float iv0 = sigm(hsum2(A00)), fv0 = sigm(hsum2(A01));
            const float gv0 = tanh_ap(hsum2(A02)), ov0 = sigm(hsum2(A03));
            const float iv1 = sigm(hsum2(A10)), fv1 = sigm(hsum2(A11));
            const float gv1 = tanh_ap(hsum2(A12)), ov1 = sigm(hsum2(A13));
            c0s = fv0 * c0s + iv0 * gv0;
            c1s = fv1 * c1s + iv1 * gv1;
            const float h20 = ov0 * tanh_ap(c0s);
            const float h21 = ov1 * tanh_ap(c1s);
            hb0[(buf ^ 1) * 32 + lane] = h20;
            hb1[(buf ^ 1) * 32 + lane] = h21;
            sy0[(t0 + tt) * HH + lane] = h20;   // dead y row -> h2 storage
            sy1[(t0 + tt) * HH + lane] = h21;
            __syncwarp();
            buf ^= 1;
        }
    }

    // ================= deferred output head =================
    const float bo = b_out[0];
    #pragma unroll 1
    for (int m = 0; m < SPW; ++m) {
        const float* sys = (m == 0) ? sy0 : sy1;
        float acc0 = 0.0f, acc1 = 0.0f;
        #pragma unroll
        for (int k = 0; k < HH; ++k) {
            const int idx = (k + lane) & 31;
            const float wv = swo[idx];
            acc0 = fmaf(sys[lane * HH + idx],        wv, acc0);
            acc1 = fmaf(sys[(lane + 32) * HH + idx], wv, acc1);
        }
        out[(size_t)(bbase + m) * SS + lane]      = acc0 + bo;
        out[(size_t)(bbase + m) * SS + lane + 32] = acc1 + bo;
    }
}

extern "C" void kernel_launch(void* const* d_in, const int* in_sizes, int n_in,
                              void* d_out, int out_size)
{
    const float* x_main = (const float*)d_in[0];
    const float* x_sfc  = (const float*)d_in[1];
    const float* w_sfc1 = (const float*)d_in[2];
    const float* b_sfc1 = (const float*)d_in[3];
    const float* w_sfc2 = (const float*)d_in[4];
    const float* b_sfc2 = (const float*)d_in[5];
    const float* w_ih1  = (const float*)d_in[6];
    const float* w_hh1  = (const float*)d_in[7];
    const float* b_ih1  = (const float*)d_in[8];
    const float* b_hh1  = (const float*)d_in[9];
    const float* w_ih2  = (const float*)d_in[10];
    const float* w_hh2  = (const float*)d_in[11];
    const float* b_ih2  = (const float*)d_in[12];
    const float* b_hh2  = (const float*)d_in[13];
    const float* w_out  = (const float*)d_in[14];
    const float* b_out  = (const float*)d_in[15];
    float* out = (float*)d_out;

    static bool attr_set = false;
    if (!attr_set) {
        cudaFuncSetAttribute(lstm_fused16, cudaFuncAttributeMaxDynamicSharedMemorySize, SMEM_BYTES);
        attr_set = true;
    }

    const int blocks = NB / BPB;   // 1024
    lstm_fused16<<<blocks, WPB * 32, SMEM_BYTES>>>(
        x_main, x_sfc, w_sfc1, b_sfc1, w_sfc2, b_sfc2,
        w_ih1, w_hh1, b_ih1, b_hh1,
        w_ih2, w_hh2, b_ih2, b_hh2,
        w_out, b_out, out);
}

// round 17
// speedup vs baseline: 2.1837x; 1.2006x over previous
#include <cuda_runtime.h>
#include <cstdint>

typedef unsigned long long u64;

#define NB   8192
#define SS   64
#define NXX  4
#define NSF  5
#define HH   32
#define WPB  4          // warps per block
#define SPW  2          // batch streams per warp
#define BPB  (WPB*SPW)  // 8 batch elements per block
#define CH   4          // layer-2 time chunk
#define FULLMASK 0xffffffffu

// ---------- packed f32x2 helpers ----------
static __device__ __forceinline__ u64 ffma2(u64 a, u64 b, u64 c) {
    u64 d; asm("fma.rn.f32x2 %0, %1, %2, %3;" : "=l"(d) : "l"(a), "l"(b), "l"(c)); return d;
}
static __device__ __forceinline__ u64 pk2(float lo, float hi) {
    u64 r; asm("mov.b64 %0, {%1, %2};" : "=l"(r) : "f"(lo), "f"(hi)); return r;
}
static __device__ __forceinline__ u64 pklo(float lo) {
    u64 r; asm("mov.b64 %0, {%1, %2};" : "=l"(r) : "f"(lo), "f"(0.0f)); return r;
}
static __device__ __forceinline__ void up2(u64 v, float& lo, float& hi) {
    asm("mov.b64 {%0, %1}, %2;" : "=f"(lo), "=f"(hi) : "l"(v));
}
static __device__ __forceinline__ float hsum2(u64 v) {
    float x, y; up2(v, x, y); return x + y;
}

// ---------- fast activations (MUFU.TANH) ----------
static __device__ __forceinline__ float tanh_ap(float x) {
    float r; asm("tanh.approx.f32 %0, %1;" : "=f"(r) : "f"(x)); return r;
}
static __device__ __forceinline__ float sigm(float x) {
    return fmaf(tanh_ap(0.5f * x), 0.5f, 0.5f);
}

// ---- shared memory (bytes) ----
// w2t : ulonglong2[2][8][128]  layer-2 weights                 32768
// sy  : float[8][64][32]       y / h2 rows (doubles as history) 65536
// hb  : float[8][32]           layer-1 h0 (t=0 history)         1024
// zb  : float[32]              zero row (layer-2 first step)     128
// swo : float[32]              w_out staged                       128
#define OFF_W2T  0
#define OFF_SY   32768
#define OFF_HB   (32768 + 65536)
#define OFF_ZB   (OFF_HB + 1024)
#define OFF_SWO  (OFF_ZB + 128)
#define SMEM_BYTES (OFF_SWO + 128)

__global__ void __launch_bounds__(WPB * 32, 2)
lstm_fused17(const float* __restrict__ x_main,
             const float* __restrict__ x_sfc,
             const float* __restrict__ w_sfc1, const float* __restrict__ b_sfc1,
             const float* __restrict__ w_sfc2, const float* __restrict__ b_sfc2,
             const float* __restrict__ w_ih1,  const float* __restrict__ w_hh1,
             const float* __restrict__ b_ih1,  const float* __restrict__ b_hh1,
             const float* __restrict__ w_ih2,  const float* __restrict__ w_hh2,
             const float* __restrict__ b_ih2,  const float* __restrict__ b_hh2,
             const float* __restrict__ w_out,  const float* __restrict__ b_out,
             float* __restrict__ out)
{
    extern __shared__ char smem[];
    ulonglong2* w2t = (ulonglong2*)(smem + OFF_W2T);   // [(m*8+qq)*128 + row]
    float* sy  = (float*)(smem + OFF_SY);
    float* hb  = (float*)(smem + OFF_HB);
    float* zb  = (float*)(smem + OFF_ZB);
    float* swo = (float*)(smem + OFF_SWO);

    const int tid  = threadIdx.x;
    const int wid  = tid >> 5;
    const int lane = tid & 31;
    const int bbase = blockIdx.x * BPB + wid * SPW;
    const int ls0   = wid * SPW;

    // ---- stage layer-2 weights + w_out + zero row ----
    #pragma unroll 4
    for (int i = tid; i < 2 * 8 * 128; i += WPB * 32) {
        const int m   = i >> 10;
        const int qq  = (i >> 7) & 7;
        const int row = i & 127;
        const float* src = (m ? w_hh2 : w_ih2) + row * HH + qq * 4;
        w2t[i] = *(const ulonglong2*)src;
    }
    if (tid < 32) { swo[tid] = w_out[tid]; zb[tid] = 0.0f; }
    __syncthreads();

    // ---- layer-1 weights -> registers ----
    u64 WR[64];    // WR[g*16 + 2qq + j]
    #pragma unroll
    for (int g = 0; g < 4; ++g) {
        const int row = g * HH + lane;
        #pragma unroll
        for (int qq = 0; qq < 8; ++qq) {
            ulonglong2 v = *(const ulonglong2*)(w_hh1 + row * HH + qq * 4);
            WR[g * 16 + 2 * qq]     = v.x;
            WR[g * 16 + 2 * qq + 1] = v.y;
        }
    }
    u64 wih[4][2], bias1p[4];
    #pragma unroll
    for (int g = 0; g < 4; ++g) {
        const int row = g * HH + lane;
        ulonglong2 vi = *(const ulonglong2*)(w_ih1 + row * NXX);
        wih[g][0] = vi.x;
        wih[g][1] = vi.y;
        bias1p[g] = pklo(b_ih1[row] + b_hh1[row]);
    }

    float* hb0 = hb + (ls0 + 0) * 32;
    float* hb1 = hb + (ls0 + 1) * 32;
    const float* x0 = x_main + (size_t)(bbase + 0) * (SS * NXX);
    const float* x1 = x_main + (size_t)(bbase + 1) * (SS * NXX);
    float* sy0 = sy + (ls0 + 0) * (SS * HH);
    float* sy1 = sy + (ls0 + 1) * (SS * HH);

    // ---- initial state from surface MLPs ----
    float c0s, c1s;
    {
        float a10 = b_sfc1[lane], a20 = b_sfc2[lane];
        float a11 = a10, a21 = a20;
        #pragma unroll
        for (int k = 0; k < NSF; ++k) {
            const float w1v = w_sfc1[lane * NSF + k];
            const float w2v = w_sfc2[lane * NSF + k];
            const float s0 = x_sfc[(bbase + 0) * NSF + k];
            const float s1 = x_sfc[(bbase + 1) * NSF + k];
            a10 += s0 * w1v;  a11 += s1 * w1v;
            a20 += s0 * w2v;  a21 += s1 * w2v;
        }
        hb0[lane] = tanh_ap(a10);
        hb1[lane] = tanh_ap(a11);
        c0s = tanh_ap(a20);
        c1s = tanh_ap(a21);
    }
    __syncwarp();

    // ================= layer 1: time-reversed scan, interleaved streams =================
    // history for step t (s = 63-t) is sy row s+1 (written last step); t=0 uses hb.
    #pragma unroll 1
    for (int t = 0; t < SS; ++t) {
        const int s = SS - 1 - t;
        const ulonglong2 xv0 = *(const ulonglong2*)(x0 + s * NXX);
        const ulonglong2 xv1 = *(const ulonglong2*)(x1 + s * NXX);

        u64 A00 = bias1p[0], A01 = bias1p[1], A02 = bias1p[2], A03 = bias1p[3];
        u64 A10 = bias1p[0], A11 = bias1p[1], A12 = bias1p[2], A13 = bias1p[3];

        A00 = ffma2(xv0.x, wih[0][0], A00);  A10 = ffma2(xv1.x, wih[0][0], A10);
        A00 = ffma2(xv0.y, wih[0][1], A00);  A10 = ffma2(xv1.y, wih[0][1], A10);
        A01 = ffma2(xv0.x, wih[1][0], A01);  A11 = ffma2(xv1.x, wih[1][0], A11);
        A01 = ffma2(xv0.y, wih[1][1], A01);  A11 = ffma2(xv1.y, wih[1][1], A11);
        A02 = ffma2(xv0.x, wih[2][0], A02);  A12 = ffma2(xv1.x, wih[2][0], A12);
        A02 = ffma2(xv0.y, wih[2][1], A02);  A12 = ffma2(xv1.y, wih[2][1], A12);
        A03 = ffma2(xv0.x, wih[3][0], A03);  A13 = ffma2(xv1.x, wih[3][0], A13);
        A03 = ffma2(xv0.y, wih[3][1], A03);  A13 = ffma2(xv1.y, wih[3][1], A13);

        const ulonglong2* hp0 =
            (const ulonglong2*)((t == 0) ? hb0 : sy0 + (s + 1) * HH);
        const ulonglong2* hp1 =
            (const ulonglong2*)((t == 0) ? hb1 : sy1 + (s + 1) * HH);
        #pragma unroll
        for (int q = 0; q < 8; ++q) {
            const ulonglong2 hv0 = hp0[q];
            const ulonglong2 hv1 = hp1[q];
            A00 = ffma2(hv0.x, WR[2*q],      A00);  A10 = ffma2(hv1.x, WR[2*q],      A10);
            A00 = ffma2(hv0.y, WR[2*q+1],    A00);  A10 = ffma2(hv1.y, WR[2*q+1],    A10);
            A01 = ffma2(hv0.x, WR[16+2*q],   A01);  A11 = ffma2(hv1.x, WR[16+2*q],   A11);
            A01 = ffma2(hv0.y, WR[16+2*q+1], A01);  A11 = ffma2(hv1.y, WR[16+2*q+1], A11);
            A02 = ffma2(hv0.x, WR[32+2*q],   A02);  A12 = ffma2(hv1.x, WR[32+2*q],   A12);
            A02 = ffma2(hv0.y, WR[32+2*q+1], A02);  A12 = ffma2(hv1.y, WR[32+2*q+1], A12);
            A03 = ffma2(hv0.x, WR[48+2*q],   A03);  A13 = ffma2(hv1.x, WR[48+2*q],   A13);
            A03 = ffma2(hv0.y, WR[48+2*q+1], A03);  A13 = ffma2(hv1.y, WR[48+2*q+1], A13);
        }

        const float iv0 = sigm(hsum2(A00)), fv0 = sigm(hsum2(A01));
        const float gv0 = tanh_ap(hsum2(A02)), ov0 = sigm(hsum2(A03));
        const float iv1 = sigm(hsum2(A10)), fv1 = sigm(hsum2(A11));
        const float gv1 = tanh_ap(hsum2(A12)), ov1 = sigm(hsum2(A13));
        c0s = fv0 * c0s + iv0 * gv0;
        c1s = fv1 * c1s + iv1 * gv1;
        const float h0 = ov0 * tanh_ap(c0s);
        const float h1 = ov1 * tanh_ap(c1s);
        sy0[s * HH + lane] = h0;
        sy1[s * HH + lane] = h1;
        __syncwarp();
    }

    // ================= layer 2: forward scan =================
    float bias2[4];
    #pragma unroll
    for (int g = 0; g < 4; ++g)
        bias2[g] = b_ih2[g * HH + lane] + b_hh2[g * HH + lane];

    c0s = 0.0f; c1s = 0.0f;

    u64 xg0[CH][2], xg1[CH][2];

    #pragma unroll 1
    for (int chk = 0; chk < SS / CH; ++chk) {
        const int t0 = chk * CH;

        // ---- phase A: input projection (w_ih2 in WR) ----
        #pragma unroll
        for (int g = 0; g < 4; ++g)
            #pragma unroll
            for (int qq = 0; qq < 8; ++qq) {
                ulonglong2 v = w2t[qq * 128 + g * 32 + lane];
                WR[g * 16 + 2 * qq]     = v.x;
                WR[g * 16 + 2 * qq + 1] = v.y;
            }
        #pragma unroll
        for (int tt = 0; tt < CH; ++tt) {
            const ulonglong2* yp0 = (const ulonglong2*)(sy0 + (t0 + tt) * HH);
            const ulonglong2* yp1 = (const ulonglong2*)(sy1 + (t0 + tt) * HH);
            u64 A00 = 0ull, A01 = 0ull, A02 = 0ull, A03 = 0ull;
            u64 A10 = 0ull, A11 = 0ull, A12 = 0ull, A13 = 0ull;
            #pragma unroll
            for (int q = 0; q < 8; ++q) {
                const ulonglong2 hv0 = yp0[q];
                const ulonglong2 hv1 = yp1[q];
                A00 = ffma2(hv0.x, WR[2*q],      A00);  A10 = ffma2(hv1.x, WR[2*q],      A10);
                A00 = ffma2(hv0.y, WR[2*q+1],    A00);  A10 = ffma2(hv1.y, WR[2*q+1],    A10);
                A01 = ffma2(hv0.x, WR[16+2*q],   A01);  A11 = ffma2(hv1.x, WR[16+2*q],   A11);
                A01 = ffma2(hv0.y, WR[16+2*q+1], A01);  A11 = ffma2(hv1.y, WR[16+2*q+1], A11);
                A02 = ffma2(hv0.x, WR[32+2*q],   A02);  A12 = ffma2(hv1.x, WR[32+2*q],   A12);
                A02 = ffma2(hv0.y, WR[32+2*q+1], A02);  A12 = ffma2(hv1.y, WR[32+2*q+1], A12);
                A03 = ffma2(hv0.x, WR[48+2*q],   A03);  A13 = ffma2(hv1.x, WR[48+2*q],   A13);
                A03 = ffma2(hv0.y, WR[48+2*q+1], A03);  A13 = ffma2(hv1.y, WR[48+2*q+1], A13);
            }
            xg0[tt][0] = pk2(hsum2(A00) + bias2[0], hsum2(A01) + bias2[1]);
            xg0[tt][1] = pk2(hsum2(A02) + bias2[2], hsum2(A03) + bias2[3]);
            xg1[tt][0] = pk2(hsum2(A10) + bias2[0], hsum2(A11) + bias2[1]);
            xg1[tt][1] = pk2(hsum2(A12) + bias2[2], hsum2(A13) + bias2[3]);
        }

        // ---- phase B: recurrence (w_hh2 in WR); h2 history lives in sy rows ----
        #pragma unroll
        for (int g = 0; g < 4; ++g)
            #pragma unroll
            for (int qq = 0; qq < 8; ++qq) {
                ulonglong2 v = w2t[1024 + qq * 128 + g * 32 + lane];
                WR[g * 16 + 2 * qq]     = v.x;
                WR[g * 16 + 2 * qq + 1] = v.y;
            }
        #pragma unroll
        for (int tt = 0; tt < CH; ++tt) {
            float x00, x01, x02, x03, x10, x11, x12, x13;
            up2(xg0[tt][0], x00, x01);
            up2(xg0[tt][1], x02, x03);
            up2(xg1[tt][0], x10, x11);
            up2(xg1[tt][1], x12, x13);
            u64 A00 = pklo(x00), A01 = pklo(x01), A02 = pklo(x02), A03 = pklo(x03);
            u64 A10 = pklo(x10), A11 = pklo(x11), A12 = pklo(x12), A13 = pklo(x13);

            const bool first = (chk == 0) && (tt == 0);
            const ulonglong2* hp0 =
                (const ulonglong2*)(first ? zb : sy0 + (t0 + tt - 1) * HH);
            const ulonglong2* hp1 =
                (const ulonglong2*)(first ? zb : sy1 + (t0 + tt - 1) * HH);
            #pragma unroll
            for (int q = 0; q < 8; ++q) {
                const ulonglong2 hv0 = hp0[q];
                const ulonglong2 hv1 = hp1[q];
                A00 = ffma2(hv0.x, WR[2*q],      A00);  A10 = ffma2(hv1.x, WR[2*q],      A10);
                A00 = ffma2(hv0.y, WR[2*q+1],    A00);  A10 = ffma2(hv1.y, WR[2*q+1],    A10);
                A01 = ffma2(hv0.x, WR[16+2*q],   A01);  A11 = ffma2(hv1.x, WR[16+2*q],   A11);
                A01 = ffma2(hv0.y, WR[16+2*q+1], A01);  A11 = ffma2(hv1.y, WR[16+2*q+1], A11);
                A02 = ffma2(hv0.x, WR[32+2*q],   A02);  A12 = ffma2(hv1.x, WR[32+2*q],   A12);
                A02 = ffma2(hv0.y, WR[32+2*q+1], A02);  A12 = ffma2(hv1.y, WR[32+2*q+1], A12);
                A03 = ffma2(hv0.x, WR[48+2*q],   A03);  A13 = ffma2(hv1.x, WR[48+2*q],   A13);
                A03 = ffma2(hv0.y, WR[48+2*q+1], A03);  A13 = ffma2(hv1.y, WR[48+2*q+1], A13);
            }
            const float iv0 = sigm(hsum2(A00)), fv0 = sigm(hsum2(A01));
            const float gv0 = tanh_ap(hsum2(A02)), ov0 = sigm(hsum2(A03));
            const float iv1 = sigm(hsum2(A10)), fv1 = sigm(hsum2(A11));
            const float gv1 = tanh_ap(hsum2(A12)), ov1 = sigm(hsum2(A13));
            c0s = fv0 * c0s + iv0 * gv0;
            c1s = fv1 * c1s + iv1 * gv1;
            const float h20 = ov0 * tanh_ap(c0s);
            const float h21 = ov1 * tanh_ap(c1s);
            sy0[(t0 + tt) * HH + lane] = h20;   // dead y row -> h2 (also history)
            sy1[(t0 + tt) * HH + lane] = h21;
            __syncwarp();
        }
    }

    // ================= deferred output head =================
    const float bo = b_out[0];
    #pragma unroll 1
    for (int m = 0; m < SPW; ++m) {
        const float* sys = (m == 0) ? sy0 : sy1;
        float acc0 = 0.0f, acc1 = 0.0f;
        #pragma unroll
        for (int k = 0; k < HH; ++k) {
            const int idx = (k + lane) & 31;
            const float wv = swo[idx];
            acc0 = fmaf(sys[lane * HH + idx],        wv, acc0);
            acc1 = fmaf(sys[(lane + 32) * HH + idx], wv, acc1);
        }
        out[(size_t)(bbase + m) * SS + lane]      = acc0 + bo;
        out[(size_t)(bbase + m) * SS + lane + 32] = acc1 + bo;
    }
}

extern "C" void kernel_launch(void* const* d_in, const int* in_sizes, int n_in,
                              void* d_out, int out_size)
{
    const float* x_main = (const float*)d_in[0];
    const float* x_sfc  = (const float*)d_in[1];
    const float* w_sfc1 = (const float*)d_in[2];
    const float* b_sfc1 = (const float*)d_in[3];
    const float* w_sfc2 = (const float*)d_in[4];
    const float* b_sfc2 = (const float*)d_in[5];
    const float* w_ih1  = (const float*)d_in[6];
    const float* w_hh1  = (const float*)d_in[7];
    const float* b_ih1  = (const float*)d_in[8];
    const float* b_hh1  = (const float*)d_in[9];
    const float* w_ih2  = (const float*)d_in[10];
    const float* w_hh2  = (const float*)d_in[11];
    const float* b_ih2  = (const float*)d_in[12];
    const float* b_hh2  = (const float*)d_in[13];
    const float* w_out  = (const float*)d_in[14];
    const float* b_out  = (const float*)d_in[15];
    float* out = (float*)d_out;

    static bool attr_set = false;
    if (!attr_set) {
        cudaFuncSetAttribute(lstm_fused17, cudaFuncAttributeMaxDynamicSharedMemorySize, SMEM_BYTES);
        attr_set = true;
    }

    const int blocks = NB / BPB;   // 1024
    lstm_fused17<<<blocks, WPB * 32, SMEM_BYTES>>>(
        x_main, x_sfc, w_sfc1, b_sfc1, w_sfc2, b_sfc2,
        w_ih1, w_hh1, b_ih1, b_hh1,
        w_ih2, w_hh2, b_ih2, b_hh2,
        w_out, b_out, out);
}